// round 17
// baseline (speedup 1.0000x reference)
#include <cuda_runtime.h>
#include <stdint.h>

// z[e, :] = h[src[e], :] * h[dst[e], :]
// h: [N=50000, D=64] fp32 (12.8 MB, L2-resident), src/dst: [E=800000] int32,
// out: [E, 64] fp32.
//
// FINAL FORM (R4 body, 4x reproduced at 39.2-39.7us wall), last probe:
// block=512 instead of 256. Warp-level body identical (8 threads/edge x
// 2 float4/thread, 4 outstanding front-batched LDG.128 gathers, __stcs
// streaming stores, full 128B-line coalescing everywhere). Halves CTA count
// -> fewer CTA launch/retire events, 2x index-line reuse per CTA. Occupancy
// unchanged (4 CTAs x 512 thr = 2048/SM cap at 28 regs).
//
// Memory-system floor reached: ~165 MB/replay DRAM write drain @ ~4.2 TB/s
// + random 256B-row gathers from L2. Falsified levers (R5-R15): MLP scaling,
// L1 bypass, SMEM+TMA store, L2 evict_last pinning, store policy, 256-bit
// accesses, persistent grid-stride.

static constexpr int D = 64;
static constexpr int VEC_PER_ROW = D / 4;   // 16 float4 per row
static constexpr int THREADS_PER_EDGE = 8;  // 2 float4 per thread
static constexpr int BLOCK = 512;

__global__ void __launch_bounds__(BLOCK, 4) u_mul_v_kernel(
    const float4* __restrict__ h,        // [N, 16] as float4
    const int* __restrict__ src,         // [E] int32
    const int* __restrict__ dst,         // [E] int32
    float4* __restrict__ out,            // [E, 16] as float4
    int n_edges)
{
    const int t = blockIdx.x * BLOCK + threadIdx.x;
    const int e = t >> 3;                // edge id
    const int j = t & 7;                 // float4 pair id within row
    if (e >= n_edges) return;

    // 8 adjacent threads read the same index -> single line, L1 broadcast.
    const int s = __ldg(&src[e]);
    const int d = __ldg(&dst[e]);

    const float4* __restrict__ hs = h + (size_t)s * VEC_PER_ROW;
    const float4* __restrict__ hd = h + (size_t)d * VEC_PER_ROW;

    // Two independent load pairs -> 4 outstanding LDG.128 per thread.
    const float4 a0 = __ldg(hs + j);
    const float4 b0 = __ldg(hd + j);
    const float4 a1 = __ldg(hs + j + 8);
    const float4 b1 = __ldg(hd + j + 8);

    float4 r0, r1;
    r0.x = a0.x * b0.x; r0.y = a0.y * b0.y;
    r0.z = a0.z * b0.z; r0.w = a0.w * b0.w;
    r1.x = a1.x * b1.x; r1.y = a1.y * b1.y;
    r1.z = a1.z * b1.z; r1.w = a1.w * b1.w;

    float4* o = out + (size_t)e * VEC_PER_ROW + j;
    __stcs(o, r0);          // streaming: don't let output evict h from L2
    __stcs(o + 8, r1);
}

extern "C" void kernel_launch(void* const* d_in, const int* in_sizes, int n_in,
                              void* d_out, int out_size) {
    const float4* h = (const float4*)d_in[0];
    const int* src = (const int*)d_in[1];
    const int* dst = (const int*)d_in[2];
    float4* out = (float4*)d_out;

    const int n_edges = in_sizes[1];  // E = 800000
    const long long total = (long long)n_edges * THREADS_PER_EDGE;
    const int blocks = (int)((total + BLOCK - 1) / BLOCK);  // 12500

    u_mul_v_kernel<<<blocks, BLOCK>>>(h, src, dst, out, n_edges);
}